// round 7
// baseline (speedup 1.0000x reference)
#include <cuda_runtime.h>

// RandomShiftsAug == integer gather from the replicate-padded (pad=4) image:
//   out[n,c,i,j] = x[n,c, clamp(i+sy-4,0,223), clamp(j+sx-4,0,223)]
// R5: MLP=16, 448-thr blocks (R4 shape). Cache policy split:
//   reads  = __ldg  (keep input L2-resident -> cross-replay L2 hits)
//   writes = __stcs (output never re-read; evict-first frees L2 for input)

#define N_   128
#define C_   9
#define H_   224
#define W_   224
#define PAD_ 4
#define ROWS_ 4
#define RY_   8   // threadIdx.y extent

__global__ __launch_bounds__(448) void random_shift_kernel(
    const float* __restrict__ x,
    const int*   __restrict__ shift,
    float*       __restrict__ out)
{
    const int nc = blockIdx.y;           // n*C_ + c, 1152 values
    const int n  = nc / C_;

    const int dx = shift[2 * n + 0] - PAD_;   // width shift,  [-4,4]
    const int dy = shift[2 * n + 1] - PAD_;   // height shift, [-4,4]

    // column indices: shared by all ROWS_ rows this thread handles
    const int j0 = threadIdx.x * 4;
    int ja = j0 + 0 + dx;
    int jb = j0 + 1 + dx;
    int jc = j0 + 2 + dx;
    int jd = j0 + 3 + dx;
    ja = ja < 0 ? 0 : (ja > W_ - 1 ? W_ - 1 : ja);
    jb = jb < 0 ? 0 : (jb > W_ - 1 ? W_ - 1 : jb);
    jc = jc < 0 ? 0 : (jc > W_ - 1 ? W_ - 1 : jc);
    jd = jd < 0 ? 0 : (jd > W_ - 1 ? W_ - 1 : jd);

    const size_t img = (size_t)nc * (H_ * W_);
    // rows handled by this thread: i0 + RY_*r
    const int i0 = blockIdx.x * (RY_ * ROWS_) + threadIdx.y;

    const float* __restrict__ src[ROWS_];
    #pragma unroll
    for (int r = 0; r < ROWS_; r++) {
        int si = i0 + RY_ * r + dy;
        si = si < 0 ? 0 : (si > H_ - 1 ? H_ - 1 : si);
        src[r] = x + img + (size_t)si * W_;
    }

    // issue all 16 loads before any store
    float4 v[ROWS_];
    #pragma unroll
    for (int r = 0; r < ROWS_; r++) {
        v[r].x = __ldg(src[r] + ja);
        v[r].y = __ldg(src[r] + jb);
        v[r].z = __ldg(src[r] + jc);
        v[r].w = __ldg(src[r] + jd);
    }

    #pragma unroll
    for (int r = 0; r < ROWS_; r++) {
        float4* dst = (float4*)(out + img + (size_t)(i0 + RY_ * r) * W_ + j0);
        __stcs(dst, v[r]);
    }
}

extern "C" void kernel_launch(void* const* d_in, const int* in_sizes, int n_in,
                              void* d_out, int out_size)
{
    const float* x     = (const float*)d_in[0];
    const int*   shift = (const int*)d_in[1];
    float*       out   = (float*)d_out;

    dim3 block(56, RY_);                       // 448 threads
    dim3 grid(H_ / (RY_ * ROWS_), N_ * C_);    // (7 row-tiles of 32 rows, 1152 nc)
    random_shift_kernel<<<grid, block>>>(x, shift, out);
}

// round 9
// speedup vs baseline: 1.0251x; 1.0251x over previous
#include <cuda_runtime.h>

// RandomShiftsAug == integer gather from the replicate-padded (pad=4) image:
//   out[n,c,i,j] = x[n,c, clamp(i+sy-4,0,223), clamp(j+sx-4,0,223)]
// R8 (resubmit; prior run died to a transient "device busy" before launch):
// interior lanes use ALIGNED LDG.128 pairs + uniform funnel select
// (dx uniform per image; rows are 128B-aligned). Cuts LDG instruction and
// L1-wavefront count ~2x vs 4x scalar LDG.32. Edge lanes (tx=0,54,55) keep
// the scalar clamped path.

#define N_   128
#define C_   9
#define H_   224
#define W_   224
#define PAD_ 4
#define ROWS_ 4
#define RY_   8

__global__ __launch_bounds__(448) void random_shift_kernel(
    const float* __restrict__ x,
    const int*   __restrict__ shift,
    float*       __restrict__ out)
{
    const int nc = blockIdx.y;            // n*C_ + c
    const int n  = nc / C_;

    const int dx = shift[2 * n + 0] - PAD_;   // [-4,4], uniform per image
    const int dy = shift[2 * n + 1] - PAD_;

    const int tx = threadIdx.x;
    const int j0 = tx * 4;
    const size_t img = (size_t)nc * (H_ * W_);
    const int i0 = blockIdx.x * (RY_ * ROWS_) + threadIdx.y;

    const float* __restrict__ src[ROWS_];
    #pragma unroll
    for (int rr = 0; rr < ROWS_; rr++) {
        int si = i0 + RY_ * rr + dy;
        si = si < 0 ? 0 : (si > H_ - 1 ? H_ - 1 : si);
        src[rr] = x + img + (size_t)si * W_;
    }

    float4 v[ROWS_];

    if (tx >= 1 && tx <= 53) {
        // interior: aligned window [a, a+7] guaranteed inside the row
        const int a = j0 + (dx & ~3);   // aligned since j0 % 4 == 0
        const int r = dx & 3;           // uniform per block; a + r == dx + j0... (a+r = j0+dx)

        if (r == 0) {
            #pragma unroll
            for (int rr = 0; rr < ROWS_; rr++)
                v[rr] = *(const float4*)(src[rr] + a);
        } else {
            float4 A[ROWS_], B[ROWS_];
            #pragma unroll
            for (int rr = 0; rr < ROWS_; rr++) {
                A[rr] = *(const float4*)(src[rr] + a);
                B[rr] = *(const float4*)(src[rr] + a + 4);
            }
            #pragma unroll
            for (int rr = 0; rr < ROWS_; rr++) {
                float4 o;
                if (r == 1)
                    o = make_float4(A[rr].y, A[rr].z, A[rr].w, B[rr].x);
                else if (r == 2)
                    o = make_float4(A[rr].z, A[rr].w, B[rr].x, B[rr].y);
                else
                    o = make_float4(A[rr].w, B[rr].x, B[rr].y, B[rr].z);
                v[rr] = o;
            }
        }
    } else {
        // edge lanes: scalar clamped gather
        int ja = j0 + 0 + dx;
        int jb = j0 + 1 + dx;
        int jc = j0 + 2 + dx;
        int jd = j0 + 3 + dx;
        ja = ja < 0 ? 0 : (ja > W_ - 1 ? W_ - 1 : ja);
        jb = jb < 0 ? 0 : (jb > W_ - 1 ? W_ - 1 : jb);
        jc = jc < 0 ? 0 : (jc > W_ - 1 ? W_ - 1 : jc);
        jd = jd < 0 ? 0 : (jd > W_ - 1 ? W_ - 1 : jd);
        #pragma unroll
        for (int rr = 0; rr < ROWS_; rr++) {
            v[rr].x = __ldg(src[rr] + ja);
            v[rr].y = __ldg(src[rr] + jb);
            v[rr].z = __ldg(src[rr] + jc);
            v[rr].w = __ldg(src[rr] + jd);
        }
    }

    #pragma unroll
    for (int rr = 0; rr < ROWS_; rr++) {
        float4* dst = (float4*)(out + img + (size_t)(i0 + RY_ * rr) * W_ + j0);
        *dst = v[rr];
    }
}

extern "C" void kernel_launch(void* const* d_in, const int* in_sizes, int n_in,
                              void* d_out, int out_size)
{
    const float* x     = (const float*)d_in[0];
    const int*   shift = (const int*)d_in[1];
    float*       out   = (float*)d_out;

    dim3 block(56, RY_);                     // 448 threads
    dim3 grid(H_ / (RY_ * ROWS_), N_ * C_);  // (7, 1152)
    random_shift_kernel<<<grid, block>>>(x, shift, out);
}